// round 14
// baseline (speedup 1.0000x reference)
#include <cuda_runtime.h>
#include <cuda_fp16.h>

#define Bn 4
#define Cn 256
#define Hn 128
#define Wn 128
#define N_ROIS 512
#define Pn 7
#define SCALE_F 0.0625f
#define GAMMA_F 0.1f

// NHWC scratch in fp16: [B, H, W, C] = 16,777,216 halves (32 MB)
__device__ __half g_xt[Bn * Hn * Wn * Cn];

// ---------------------------------------------------------------------------
// NCHW(fp32) -> NHWC(fp16) transpose (proven schedule; x reads streamed via
// __ldcs so the read-once 128MB stream doesn't evict g_xt from L2).
// ---------------------------------------------------------------------------
__global__ void __launch_bounds__(256) transpose_nchw_nhwc(const float* __restrict__ x) {
    __shared__ float tile[32][33];
    const int bhy = blockIdx.z;          // b*H + y
    const int b = bhy >> 7;
    const int y = bhy & 127;
    const int w0 = blockIdx.x * 32;
    const int tid = threadIdx.x;

    const int cl = tid >> 3;             // 0..31 channel row (load)
    const int w4 = (tid & 7) * 4;        // 0..28 w quad (load)
    const int wl = tid >> 3;             // 0..31 w (store)
    const int c4 = (tid & 7) * 4;        // 0..28 c quad (store)

#pragma unroll
    for (int ct = 0; ct < 4; ct++) {
        const int c0 = blockIdx.y * 128 + ct * 32;
        const float4 v = __ldcs((const float4*)(x + (((size_t)(b * Cn + c0 + cl) * Hn + y) * Wn + w0 + w4)));
        tile[cl][w4 + 0] = v.x;
        tile[cl][w4 + 1] = v.y;
        tile[cl][w4 + 2] = v.z;
        tile[cl][w4 + 3] = v.w;
        __syncthreads();
        __half2 ha = __floats2half2_rn(tile[c4 + 0][wl], tile[c4 + 1][wl]);
        __half2 hb = __floats2half2_rn(tile[c4 + 2][wl], tile[c4 + 3][wl]);
        uint2 u;
        u.x = *reinterpret_cast<unsigned*>(&ha);
        u.y = *reinterpret_cast<unsigned*>(&hb);
        *(uint2*)(g_xt + ((size_t)(bhy * Wn + w0 + wl) * Cn + c0 + c4)) = u;
        __syncthreads();
    }
}

// ---------------------------------------------------------------------------
// Deformable ROI pool. One block per ROI, 512 threads, 2 CTAs/SM, ~64 regs.
// Warp w (0..15) handles ADJACENT bins {3w, 3w+1, 3w+2} (+48 for w=0):
// concurrent chains share ~half their cache lines (patches overlap in x),
// and the third bin re-hits L1 lines from the pair.
// Per row: x-weighting in half2 (HMUL2/HFMA2), fp32 wy accumulation.
// ---------------------------------------------------------------------------
#define SOUT_PITCH 260   // 16B-aligned rows

__device__ __forceinline__ __half2 h2(unsigned u) {
    return *reinterpret_cast<__half2*>(&u);
}

__device__ __forceinline__ void gather_bin(
    const __half* __restrict__ base,
    const float*  __restrict__ s_w,
    const int*    __restrict__ s_off,
    int bin, float4& accLo, float4& accHi)
{
    const float4 wy4 = *(const float4*)(s_w + bin * 8);
    const uint4  wxu = *(const uint4*)(s_w + bin * 8 + 4);
    const int4 ro = ((const int4*)(s_off + bin * 8))[0];
    const int4 co = ((const int4*)(s_off + bin * 8))[1];
    const int rr[4] = {ro.x, ro.y, ro.z, ro.w};
    const int cc[4] = {co.x, co.y, co.z, co.w};
    const float wyA[4] = {wy4.x, wy4.y, wy4.z, wy4.w};
    const __half2 w0 = h2(wxu.x), w1 = h2(wxu.y), w2 = h2(wxu.z), w3 = h2(wxu.w);

    float4 lo = make_float4(0.f, 0.f, 0.f, 0.f);
    float4 hi = make_float4(0.f, 0.f, 0.f, 0.f);
#pragma unroll
    for (int r = 0; r < 4; r++) {
        const __half* rp = base + rr[r];
        uint4 u0 = *(const uint4*)(rp + cc[0]);
        uint4 u1 = *(const uint4*)(rp + cc[1]);
        uint4 u2 = *(const uint4*)(rp + cc[2]);
        uint4 u3 = *(const uint4*)(rp + cc[3]);

        __half2 a0 = __hmul2(h2(u0.x), w0);
        __half2 a1 = __hmul2(h2(u0.y), w0);
        __half2 a2 = __hmul2(h2(u0.z), w0);
        __half2 a3 = __hmul2(h2(u0.w), w0);
        a0 = __hfma2(h2(u1.x), w1, a0);
        a1 = __hfma2(h2(u1.y), w1, a1);
        a2 = __hfma2(h2(u1.z), w1, a2);
        a3 = __hfma2(h2(u1.w), w1, a3);
        a0 = __hfma2(h2(u2.x), w2, a0);
        a1 = __hfma2(h2(u2.y), w2, a1);
        a2 = __hfma2(h2(u2.z), w2, a2);
        a3 = __hfma2(h2(u2.w), w2, a3);
        a0 = __hfma2(h2(u3.x), w3, a0);
        a1 = __hfma2(h2(u3.y), w3, a1);
        a2 = __hfma2(h2(u3.z), w3, a2);
        a3 = __hfma2(h2(u3.w), w3, a3);

        const float wr = wyA[r];
        const float2 f0 = __half22float2(a0);
        const float2 f1 = __half22float2(a1);
        const float2 f2 = __half22float2(a2);
        const float2 f3 = __half22float2(a3);
        lo.x = fmaf(wr, f0.x, lo.x); lo.y = fmaf(wr, f0.y, lo.y);
        lo.z = fmaf(wr, f1.x, lo.z); lo.w = fmaf(wr, f1.y, lo.w);
        hi.x = fmaf(wr, f2.x, hi.x); hi.y = fmaf(wr, f2.y, hi.y);
        hi.z = fmaf(wr, f3.x, hi.z); hi.w = fmaf(wr, f3.y, hi.w);
    }
    accLo = lo;
    accHi = hi;
}

__global__ void __launch_bounds__(512, 2) dcn_pool_kernel(
    const float* __restrict__ rois,
    const float* __restrict__ offset,
    float* __restrict__ out)
{
    extern __shared__ float smem[];
    float* s_out = smem;                           // 49*260 floats
    float* s_w   = smem + 49 * SOUT_PITCH;         // 49*8 (wy f32 x4 | wx half2 x4)
    int*   s_off = (int*)(s_w + 49 * 8);           // 49*8 (ro x4 | co x4)

    const int n = blockIdx.x;
    const int tid = threadIdx.x;

    const int bidx = (int)rois[n * 5 + 0];

    if (tid < 49) {
        const float x1 = rois[n * 5 + 1] * SCALE_F - 0.5f;
        const float y1 = rois[n * 5 + 2] * SCALE_F - 0.5f;
        const float x2 = rois[n * 5 + 3] * SCALE_F - 0.5f;
        const float y2 = rois[n * 5 + 4] * SCALE_F - 0.5f;
        const float rw = fmaxf(x2 - x1, 1.0f);
        const float rh = fmaxf(y2 - y1, 1.0f);
        const float bw = rw * (1.0f / Pn);
        const float bh = rh * (1.0f / Pn);

        const int ph = tid / 7;
        const int pw = tid - ph * 7;
        const float ox = offset[n * 98 + tid];
        const float oy = offset[n * 98 + 49 + tid];
        const float ybase = y1 + (float)ph * bh + GAMMA_F * rh * oy;
        const float xbase = x1 + (float)pw * bw + GAMMA_F * rw * ox;

        // ---- y direction: 4 samples -> weights over 4 contiguous rows ----
        float wy[4] = {0.f, 0.f, 0.f, 0.f};
        int   y0a[4];
        float lya[4], va[4];
        int rmin = Hn;
#pragma unroll
        for (int i = 0; i < 4; i++) {
            const float s  = ((float)i + 0.5f) * 0.25f;
            const float ys = ybase + s * bh;
            const float v  = (ys > -1.0f && ys < (float)Hn) ? 0.25f : 0.0f;
            const float yc = fminf(fmaxf(ys, 0.0f), (float)(Hn - 1));
            const int   y0 = (int)yc;
            y0a[i] = y0; lya[i] = yc - (float)y0; va[i] = v;
            rmin = min(rmin, y0);
        }
#pragma unroll
        for (int i = 0; i < 4; i++) {
            const int sl0 = min(y0a[i] - rmin, 3);
            const int sl1 = min(min(y0a[i] + 1, Hn - 1) - rmin, 3);
            wy[sl0] += (1.0f - lya[i]) * va[i];
            wy[sl1] += lya[i] * va[i];
        }

        // ---- x direction ----
        float wx[4] = {0.f, 0.f, 0.f, 0.f};
        int   x0a[4];
        float lxa[4], vxa[4];
        int cmin = Wn;
#pragma unroll
        for (int j = 0; j < 4; j++) {
            const float s  = ((float)j + 0.5f) * 0.25f;
            const float xs = xbase + s * bw;
            const float v  = (xs > -1.0f && xs < (float)Wn) ? 0.25f : 0.0f;
            const float xc = fminf(fmaxf(xs, 0.0f), (float)(Wn - 1));
            const int   x0 = (int)xc;
            x0a[j] = x0; lxa[j] = xc - (float)x0; vxa[j] = v;
            cmin = min(cmin, x0);
        }
#pragma unroll
        for (int j = 0; j < 4; j++) {
            const int sl0 = min(x0a[j] - cmin, 3);
            const int sl1 = min(min(x0a[j] + 1, Wn - 1) - cmin, 3);
            wx[sl0] += (1.0f - lxa[j]) * vxa[j];
            wx[sl1] += lxa[j] * vxa[j];
        }

        // ---- record: wy (f32 x4) | wx (half2-broadcast x4) ; ro x4 | co x4 ----
#pragma unroll
        for (int k = 0; k < 4; k++) {
            s_w[tid * 8 + k] = wy[k];
            const unsigned short hb = __half_as_ushort(__float2half_rn(wx[k]));
            ((unsigned*)s_w)[tid * 8 + 4 + k] = (unsigned)hb * 0x10001u;
            s_off[tid * 8 + k]     = min(rmin + k, Hn - 1) * (Wn * Cn);
            s_off[tid * 8 + 4 + k] = min(cmin + k, Wn - 1) * Cn;
        }
    }
    __syncthreads();

    // ---- gather: warp w handles adjacent bins {3w, 3w+1, 3w+2} (+48 if w==0)
    const int c8 = tid & 31;
    const int w  = tid >> 5;             // warp 0..15
    const __half* base = g_xt + (size_t)(bidx * Hn * Wn) * Cn + c8 * 8;
    float* sout_row = s_out + c8 * 8;

    const int b0 = 3 * w;
    {   // pair (b0, b0+1): concurrent chains on overlapping patches
        float4 aLo, aHi, bLo, bHi;
        gather_bin(base, s_w, s_off, b0,     aLo, aHi);
        gather_bin(base, s_w, s_off, b0 + 1, bLo, bHi);
        *(float4*)(sout_row + b0       * SOUT_PITCH)     = aLo;
        *(float4*)(sout_row + b0       * SOUT_PITCH + 4) = aHi;
        *(float4*)(sout_row + (b0 + 1) * SOUT_PITCH)     = bLo;
        *(float4*)(sout_row + (b0 + 1) * SOUT_PITCH + 4) = bHi;
    }
    {   // third bin: re-hits lines loaded by the pair
        float4 aLo, aHi;
        gather_bin(base, s_w, s_off, b0 + 2, aLo, aHi);
        *(float4*)(sout_row + (b0 + 2) * SOUT_PITCH)     = aLo;
        *(float4*)(sout_row + (b0 + 2) * SOUT_PITCH + 4) = aHi;
    }
    if (w == 0) {  // bin 48
        float4 aLo, aHi;
        gather_bin(base, s_w, s_off, 48, aLo, aHi);
        *(float4*)(sout_row + 48 * SOUT_PITCH)     = aLo;
        *(float4*)(sout_row + 48 * SOUT_PITCH + 4) = aHi;
    }
    __syncthreads();

    // ---- coalesced store of the ROI's contiguous [C][49] output chunk ----
    float* o = out + (size_t)n * (Cn * 49);
    for (int l = tid; l < Cn * 49; l += 512) {
        const int c = l / 49;
        const int b = l - c * 49;
        o[l] = s_out[b * SOUT_PITCH + c];
    }
}

extern "C" void kernel_launch(void* const* d_in, const int* in_sizes, int n_in,
                              void* d_out, int out_size) {
    const float* x      = (const float*)d_in[0];
    const float* rois   = (const float*)d_in[1];
    const float* offset = (const float*)d_in[2];
    float* out = (float*)d_out;

    // NCHW fp32 -> NHWC fp16
    dim3 tgrid(Wn / 32, Cn / 128, Bn * Hn);
    transpose_nchw_nhwc<<<tgrid, 256>>>(x);

    const int smem_bytes = (49 * SOUT_PITCH + 49 * 8) * sizeof(float) + 49 * 8 * sizeof(int);
    static bool attr_set = false;
    if (!attr_set) {
        cudaFuncSetAttribute(dcn_pool_kernel,
                             cudaFuncAttributeMaxDynamicSharedMemorySize, smem_bytes);
        attr_set = true;
    }
    dcn_pool_kernel<<<N_ROIS, 512, smem_bytes>>>(rois, offset, out);
}

// round 16
// speedup vs baseline: 1.1021x; 1.1021x over previous
#include <cuda_runtime.h>
#include <cuda_fp16.h>

#define Bn 4
#define Cn 256
#define Hn 128
#define Wn 128
#define N_ROIS 512
#define Pn 7
#define SCALE_F 0.0625f
#define GAMMA_F 0.1f

// NHWC scratch in fp16: [B, H, W, C] = 16,777,216 halves (32 MB)
__device__ __half g_xt[Bn * Hn * Wn * Cn];

// ---- L2 cache-policy helpers (policy-operand form: legal for all widths) ----
__device__ __forceinline__ unsigned long long pol_evict_first() {
    unsigned long long p;
    asm("createpolicy.fractional.L2::evict_first.b64 %0, 1.0;" : "=l"(p));
    return p;
}
__device__ __forceinline__ unsigned long long pol_evict_last() {
    unsigned long long p;
    asm("createpolicy.fractional.L2::evict_last.b64 %0, 1.0;" : "=l"(p));
    return p;
}
__device__ __forceinline__ float4 ld_f4_ef(const float* p, unsigned long long pol) {
    float4 v;
    asm volatile("ld.global.nc.L2::cache_hint.v4.f32 {%0,%1,%2,%3}, [%4], %5;"
                 : "=f"(v.x), "=f"(v.y), "=f"(v.z), "=f"(v.w)
                 : "l"(p), "l"(pol));
    return v;
}
__device__ __forceinline__ void st_u2_el(__half* p, uint2 u, unsigned long long pol) {
    asm volatile("st.global.L2::cache_hint.v2.b32 [%0], {%1,%2}, %3;"
                 :: "l"(p), "r"(u.x), "r"(u.y), "l"(pol) : "memory");
}

// ---------------------------------------------------------------------------
// NCHW(fp32) -> NHWC(fp16) transpose (proven R9 schedule).
// x reads: evict_first (read-once stream, don't pollute L2).
// g_xt stores: evict_last (pin the 32MB working set in L2 for the pool).
// ---------------------------------------------------------------------------
__global__ void __launch_bounds__(256) transpose_nchw_nhwc(const float* __restrict__ x) {
    __shared__ float tile[32][33];
    const int bhy = blockIdx.z;          // b*H + y
    const int b = bhy >> 7;
    const int y = bhy & 127;
    const int w0 = blockIdx.x * 32;
    const int tid = threadIdx.x;

    const unsigned long long pf = pol_evict_first();
    const unsigned long long pl = pol_evict_last();

    const int cl = tid >> 3;             // 0..31 channel row (load)
    const int w4 = (tid & 7) * 4;        // 0..28 w quad (load)
    const int wl = tid >> 3;             // 0..31 w (store)
    const int c4 = (tid & 7) * 4;        // 0..28 c quad (store)

#pragma unroll
    for (int ct = 0; ct < 4; ct++) {
        const int c0 = blockIdx.y * 128 + ct * 32;
        const float4 v = ld_f4_ef(x + (((size_t)(b * Cn + c0 + cl) * Hn + y) * Wn + w0 + w4), pf);
        tile[cl][w4 + 0] = v.x;
        tile[cl][w4 + 1] = v.y;
        tile[cl][w4 + 2] = v.z;
        tile[cl][w4 + 3] = v.w;
        __syncthreads();
        __half2 ha = __floats2half2_rn(tile[c4 + 0][wl], tile[c4 + 1][wl]);
        __half2 hb = __floats2half2_rn(tile[c4 + 2][wl], tile[c4 + 3][wl]);
        uint2 u;
        u.x = *reinterpret_cast<unsigned*>(&ha);
        u.y = *reinterpret_cast<unsigned*>(&hb);
        st_u2_el(g_xt + ((size_t)(bhy * Wn + w0 + wl) * Cn + c0 + c4), u, pl);
        __syncthreads();
    }
}

// ---------------------------------------------------------------------------
// Deformable ROI pool (R12 proven, byte-identical: 23.9us). One block per
// ROI, 512 threads, 2 CTAs/SM. Thread = (bin-slice tid>>5) x (chan-oct tid&31).
// Per row: x-weighting in half2 (HMUL2/HFMA2), fp32 wy accumulation.
// ---------------------------------------------------------------------------
#define SOUT_PITCH 260   // 16B-aligned rows

__device__ __forceinline__ __half2 h2(unsigned u) {
    return *reinterpret_cast<__half2*>(&u);
}

__device__ __forceinline__ void gather_bin(
    const __half* __restrict__ base,
    const float*  __restrict__ s_w,
    const int*    __restrict__ s_off,
    int bin, float4& accLo, float4& accHi)
{
    const float4 wy4 = *(const float4*)(s_w + bin * 8);
    const uint4  wxu = *(const uint4*)(s_w + bin * 8 + 4);
    const int4 ro = ((const int4*)(s_off + bin * 8))[0];
    const int4 co = ((const int4*)(s_off + bin * 8))[1];
    const int rr[4] = {ro.x, ro.y, ro.z, ro.w};
    const int cc[4] = {co.x, co.y, co.z, co.w};
    const float wyA[4] = {wy4.x, wy4.y, wy4.z, wy4.w};
    const __half2 w0 = h2(wxu.x), w1 = h2(wxu.y), w2 = h2(wxu.z), w3 = h2(wxu.w);

    float4 lo = make_float4(0.f, 0.f, 0.f, 0.f);
    float4 hi = make_float4(0.f, 0.f, 0.f, 0.f);
#pragma unroll
    for (int r = 0; r < 4; r++) {
        const __half* rp = base + rr[r];
        uint4 u0 = *(const uint4*)(rp + cc[0]);
        uint4 u1 = *(const uint4*)(rp + cc[1]);
        uint4 u2 = *(const uint4*)(rp + cc[2]);
        uint4 u3 = *(const uint4*)(rp + cc[3]);

        __half2 a0 = __hmul2(h2(u0.x), w0);
        __half2 a1 = __hmul2(h2(u0.y), w0);
        __half2 a2 = __hmul2(h2(u0.z), w0);
        __half2 a3 = __hmul2(h2(u0.w), w0);
        a0 = __hfma2(h2(u1.x), w1, a0);
        a1 = __hfma2(h2(u1.y), w1, a1);
        a2 = __hfma2(h2(u1.z), w1, a2);
        a3 = __hfma2(h2(u1.w), w1, a3);
        a0 = __hfma2(h2(u2.x), w2, a0);
        a1 = __hfma2(h2(u2.y), w2, a1);
        a2 = __hfma2(h2(u2.z), w2, a2);
        a3 = __hfma2(h2(u2.w), w2, a3);
        a0 = __hfma2(h2(u3.x), w3, a0);
        a1 = __hfma2(h2(u3.y), w3, a1);
        a2 = __hfma2(h2(u3.z), w3, a2);
        a3 = __hfma2(h2(u3.w), w3, a3);

        const float wr = wyA[r];
        const float2 f0 = __half22float2(a0);
        const float2 f1 = __half22float2(a1);
        const float2 f2 = __half22float2(a2);
        const float2 f3 = __half22float2(a3);
        lo.x = fmaf(wr, f0.x, lo.x); lo.y = fmaf(wr, f0.y, lo.y);
        lo.z = fmaf(wr, f1.x, lo.z); lo.w = fmaf(wr, f1.y, lo.w);
        hi.x = fmaf(wr, f2.x, hi.x); hi.y = fmaf(wr, f2.y, hi.y);
        hi.z = fmaf(wr, f3.x, hi.z); hi.w = fmaf(wr, f3.y, hi.w);
    }
    accLo = lo;
    accHi = hi;
}

__global__ void __launch_bounds__(512, 2) dcn_pool_kernel(
    const float* __restrict__ rois,
    const float* __restrict__ offset,
    float* __restrict__ out)
{
    extern __shared__ float smem[];
    float* s_out = smem;                           // 49*260 floats
    float* s_w   = smem + 49 * SOUT_PITCH;         // 49*8 (wy f32 x4 | wx half2 x4)
    int*   s_off = (int*)(s_w + 49 * 8);           // 49*8 (ro x4 | co x4)

    const int n = blockIdx.x;
    const int tid = threadIdx.x;

    const int bidx = (int)rois[n * 5 + 0];

    if (tid < 49) {
        const float x1 = rois[n * 5 + 1] * SCALE_F - 0.5f;
        const float y1 = rois[n * 5 + 2] * SCALE_F - 0.5f;
        const float x2 = rois[n * 5 + 3] * SCALE_F - 0.5f;
        const float y2 = rois[n * 5 + 4] * SCALE_F - 0.5f;
        const float rw = fmaxf(x2 - x1, 1.0f);
        const float rh = fmaxf(y2 - y1, 1.0f);
        const float bw = rw * (1.0f / Pn);
        const float bh = rh * (1.0f / Pn);

        const int ph = tid / 7;
        const int pw = tid - ph * 7;
        const float ox = offset[n * 98 + tid];
        const float oy = offset[n * 98 + 49 + tid];
        const float ybase = y1 + (float)ph * bh + GAMMA_F * rh * oy;
        const float xbase = x1 + (float)pw * bw + GAMMA_F * rw * ox;

        // ---- y direction: 4 samples -> weights over 4 contiguous rows ----
        float wy[4] = {0.f, 0.f, 0.f, 0.f};
        int   y0a[4];
        float lya[4], va[4];
        int rmin = Hn;
#pragma unroll
        for (int i = 0; i < 4; i++) {
            const float s  = ((float)i + 0.5f) * 0.25f;
            const float ys = ybase + s * bh;
            const float v  = (ys > -1.0f && ys < (float)Hn) ? 0.25f : 0.0f;
            const float yc = fminf(fmaxf(ys, 0.0f), (float)(Hn - 1));
            const int   y0 = (int)yc;
            y0a[i] = y0; lya[i] = yc - (float)y0; va[i] = v;
            rmin = min(rmin, y0);
        }
#pragma unroll
        for (int i = 0; i < 4; i++) {
            const int sl0 = min(y0a[i] - rmin, 3);
            const int sl1 = min(min(y0a[i] + 1, Hn - 1) - rmin, 3);
            wy[sl0] += (1.0f - lya[i]) * va[i];
            wy[sl1] += lya[i] * va[i];
        }

        // ---- x direction ----
        float wx[4] = {0.f, 0.f, 0.f, 0.f};
        int   x0a[4];
        float lxa[4], vxa[4];
        int cmin = Wn;
#pragma unroll
        for (int j = 0; j < 4; j++) {
            const float s  = ((float)j + 0.5f) * 0.25f;
            const float xs = xbase + s * bw;
            const float v  = (xs > -1.0f && xs < (float)Wn) ? 0.25f : 0.0f;
            const float xc = fminf(fmaxf(xs, 0.0f), (float)(Wn - 1));
            const int   x0 = (int)xc;
            x0a[j] = x0; lxa[j] = xc - (float)x0; vxa[j] = v;
            cmin = min(cmin, x0);
        }
#pragma unroll
        for (int j = 0; j < 4; j++) {
            const int sl0 = min(x0a[j] - cmin, 3);
            const int sl1 = min(min(x0a[j] + 1, Wn - 1) - cmin, 3);
            wx[sl0] += (1.0f - lxa[j]) * vxa[j];
            wx[sl1] += lxa[j] * vxa[j];
        }

        // ---- record: wy (f32 x4) | wx (half2-broadcast x4) ; ro x4 | co x4 ----
#pragma unroll
        for (int k = 0; k < 4; k++) {
            s_w[tid * 8 + k] = wy[k];
            const unsigned short hb = __half_as_ushort(__float2half_rn(wx[k]));
            ((unsigned*)s_w)[tid * 8 + 4 + k] = (unsigned)hb * 0x10001u;
            s_off[tid * 8 + k]     = min(rmin + k, Hn - 1) * (Wn * Cn);
            s_off[tid * 8 + 4 + k] = min(cmin + k, Wn - 1) * Cn;
        }
    }
    __syncthreads();

    // ---- gather: thread = (bin slice bs 0..15) x (channel oct c8 0..31) ----
    const int c8 = tid & 31;
    const int bs = tid >> 5;
    const __half* base = g_xt + (size_t)(bidx * Hn * Wn) * Cn + c8 * 8;
    float* sout_row = s_out + c8 * 8;

    // 2-bin unrolled: pairs (bin, bin+16), stride 32
    int bin = bs;
    for (; bin + 16 < 49; bin += 32) {
        float4 aLo, aHi, bLo, bHi;
        gather_bin(base, s_w, s_off, bin,      aLo, aHi);
        gather_bin(base, s_w, s_off, bin + 16, bLo, bHi);
        *(float4*)(sout_row + bin        * SOUT_PITCH)     = aLo;
        *(float4*)(sout_row + bin        * SOUT_PITCH + 4) = aHi;
        *(float4*)(sout_row + (bin + 16) * SOUT_PITCH)     = bLo;
        *(float4*)(sout_row + (bin + 16) * SOUT_PITCH + 4) = bHi;
    }
    for (; bin < 49; bin += 16) {
        float4 aLo, aHi;
        gather_bin(base, s_w, s_off, bin, aLo, aHi);
        *(float4*)(sout_row + bin * SOUT_PITCH)     = aLo;
        *(float4*)(sout_row + bin * SOUT_PITCH + 4) = aHi;
    }
    __syncthreads();

    // ---- coalesced store of the ROI's contiguous [C][49] output chunk ----
    float* o = out + (size_t)n * (Cn * 49);
    for (int l = tid; l < Cn * 49; l += 512) {
        const int c = l / 49;
        const int b = l - c * 49;
        o[l] = s_out[b * SOUT_PITCH + c];
    }
}

extern "C" void kernel_launch(void* const* d_in, const int* in_sizes, int n_in,
                              void* d_out, int out_size) {
    const float* x      = (const float*)d_in[0];
    const float* rois   = (const float*)d_in[1];
    const float* offset = (const float*)d_in[2];
    float* out = (float*)d_out;

    // NCHW fp32 -> NHWC fp16
    dim3 tgrid(Wn / 32, Cn / 128, Bn * Hn);
    transpose_nchw_nhwc<<<tgrid, 256>>>(x);

    const int smem_bytes = (49 * SOUT_PITCH + 49 * 8) * sizeof(float) + 49 * 8 * sizeof(int);
    static bool attr_set = false;
    if (!attr_set) {
        cudaFuncSetAttribute(dcn_pool_kernel,
                             cudaFuncAttributeMaxDynamicSharedMemorySize, smem_bytes);
        attr_set = true;
    }
    dcn_pool_kernel<<<N_ROIS, 512, smem_bytes>>>(rois, offset, out);
}

// round 17
// speedup vs baseline: 1.1667x; 1.0586x over previous
#include <cuda_runtime.h>
#include <cuda_fp16.h>

#define Bn 4
#define Cn 256
#define Hn 128
#define Wn 128
#define N_ROIS 512
#define Pn 7
#define SCALE_F 0.0625f
#define GAMMA_F 0.1f

// NHWC scratch in fp16: [B, H, W, C] = 16,777,216 halves (32 MB)
__device__ __half g_xt[Bn * Hn * Wn * Cn];

// ---- L2 cache-policy helpers (policy-operand form: legal for all widths) ----
__device__ __forceinline__ unsigned long long pol_evict_first() {
    unsigned long long p;
    asm("createpolicy.fractional.L2::evict_first.b64 %0, 1.0;" : "=l"(p));
    return p;
}
__device__ __forceinline__ unsigned long long pol_evict_last() {
    unsigned long long p;
    asm("createpolicy.fractional.L2::evict_last.b64 %0, 1.0;" : "=l"(p));
    return p;
}
__device__ __forceinline__ float4 ld_f4_ef(const float* p, unsigned long long pol) {
    float4 v;
    asm volatile("ld.global.nc.L2::cache_hint.v4.f32 {%0,%1,%2,%3}, [%4], %5;"
                 : "=f"(v.x), "=f"(v.y), "=f"(v.z), "=f"(v.w)
                 : "l"(p), "l"(pol));
    return v;
}
__device__ __forceinline__ void st_u2_el(__half* p, uint2 u, unsigned long long pol) {
    asm volatile("st.global.L2::cache_hint.v2.b32 [%0], {%1,%2}, %3;"
                 :: "l"(p), "r"(u.x), "r"(u.y), "l"(pol) : "memory");
}

// ---------------------------------------------------------------------------
// NCHW(fp32) -> NHWC(fp16) transpose (proven R16 version, ~13.2us).
// x reads: evict_first (read-once stream). g_xt stores: evict_last (pin in L2).
// ---------------------------------------------------------------------------
__global__ void __launch_bounds__(256) transpose_nchw_nhwc(const float* __restrict__ x) {
    __shared__ float tile[32][33];
    const int bhy = blockIdx.z;          // b*H + y
    const int b = bhy >> 7;
    const int y = bhy & 127;
    const int w0 = blockIdx.x * 32;
    const int tid = threadIdx.x;

    const unsigned long long pf = pol_evict_first();
    const unsigned long long pl = pol_evict_last();

    const int cl = tid >> 3;             // 0..31 channel row (load)
    const int w4 = (tid & 7) * 4;        // 0..28 w quad (load)
    const int wl = tid >> 3;             // 0..31 w (store)
    const int c4 = (tid & 7) * 4;        // 0..28 c quad (store)

#pragma unroll
    for (int ct = 0; ct < 4; ct++) {
        const int c0 = blockIdx.y * 128 + ct * 32;
        const float4 v = ld_f4_ef(x + (((size_t)(b * Cn + c0 + cl) * Hn + y) * Wn + w0 + w4), pf);
        tile[cl][w4 + 0] = v.x;
        tile[cl][w4 + 1] = v.y;
        tile[cl][w4 + 2] = v.z;
        tile[cl][w4 + 3] = v.w;
        __syncthreads();
        __half2 ha = __floats2half2_rn(tile[c4 + 0][wl], tile[c4 + 1][wl]);
        __half2 hb = __floats2half2_rn(tile[c4 + 2][wl], tile[c4 + 3][wl]);
        uint2 u;
        u.x = *reinterpret_cast<unsigned*>(&ha);
        u.y = *reinterpret_cast<unsigned*>(&hb);
        st_u2_el(g_xt + ((size_t)(bhy * Wn + w0 + wl) * Cn + c0 + c4), u, pl);
        __syncthreads();
    }
}

// ---------------------------------------------------------------------------
// Deformable ROI pool (R12 gather, proven). One block per ROI, 512 threads,
// 2 CTAs/SM. Output stores use __stcs (streaming) so the 25.7MB write stream
// doesn't evict the L2-pinned g_xt mid-kernel.
// ---------------------------------------------------------------------------
#define SOUT_PITCH 260   // 16B-aligned rows

__device__ __forceinline__ __half2 h2(unsigned u) {
    return *reinterpret_cast<__half2*>(&u);
}

__device__ __forceinline__ void gather_bin(
    const __half* __restrict__ base,
    const float*  __restrict__ s_w,
    const int*    __restrict__ s_off,
    int bin, float4& accLo, float4& accHi)
{
    const float4 wy4 = *(const float4*)(s_w + bin * 8);
    const uint4  wxu = *(const uint4*)(s_w + bin * 8 + 4);
    const int4 ro = ((const int4*)(s_off + bin * 8))[0];
    const int4 co = ((const int4*)(s_off + bin * 8))[1];
    const int rr[4] = {ro.x, ro.y, ro.z, ro.w};
    const int cc[4] = {co.x, co.y, co.z, co.w};
    const float wyA[4] = {wy4.x, wy4.y, wy4.z, wy4.w};
    const __half2 w0 = h2(wxu.x), w1 = h2(wxu.y), w2 = h2(wxu.z), w3 = h2(wxu.w);

    float4 lo = make_float4(0.f, 0.f, 0.f, 0.f);
    float4 hi = make_float4(0.f, 0.f, 0.f, 0.f);
#pragma unroll
    for (int r = 0; r < 4; r++) {
        const __half* rp = base + rr[r];
        uint4 u0 = *(const uint4*)(rp + cc[0]);
        uint4 u1 = *(const uint4*)(rp + cc[1]);
        uint4 u2 = *(const uint4*)(rp + cc[2]);
        uint4 u3 = *(const uint4*)(rp + cc[3]);

        __half2 a0 = __hmul2(h2(u0.x), w0);
        __half2 a1 = __hmul2(h2(u0.y), w0);
        __half2 a2 = __hmul2(h2(u0.z), w0);
        __half2 a3 = __hmul2(h2(u0.w), w0);
        a0 = __hfma2(h2(u1.x), w1, a0);
        a1 = __hfma2(h2(u1.y), w1, a1);
        a2 = __hfma2(h2(u1.z), w1, a2);
        a3 = __hfma2(h2(u1.w), w1, a3);
        a0 = __hfma2(h2(u2.x), w2, a0);
        a1 = __hfma2(h2(u2.y), w2, a1);
        a2 = __hfma2(h2(u2.z), w2, a2);
        a3 = __hfma2(h2(u2.w), w2, a3);
        a0 = __hfma2(h2(u3.x), w3, a0);
        a1 = __hfma2(h2(u3.y), w3, a1);
        a2 = __hfma2(h2(u3.z), w3, a2);
        a3 = __hfma2(h2(u3.w), w3, a3);

        const float wr = wyA[r];
        const float2 f0 = __half22float2(a0);
        const float2 f1 = __half22float2(a1);
        const float2 f2 = __half22float2(a2);
        const float2 f3 = __half22float2(a3);
        lo.x = fmaf(wr, f0.x, lo.x); lo.y = fmaf(wr, f0.y, lo.y);
        lo.z = fmaf(wr, f1.x, lo.z); lo.w = fmaf(wr, f1.y, lo.w);
        hi.x = fmaf(wr, f2.x, hi.x); hi.y = fmaf(wr, f2.y, hi.y);
        hi.z = fmaf(wr, f3.x, hi.z); hi.w = fmaf(wr, f3.y, hi.w);
    }
    accLo = lo;
    accHi = hi;
}

__global__ void __launch_bounds__(512, 2) dcn_pool_kernel(
    const float* __restrict__ rois,
    const float* __restrict__ offset,
    float* __restrict__ out)
{
    extern __shared__ float smem[];
    float* s_out = smem;                           // 49*260 floats
    float* s_w   = smem + 49 * SOUT_PITCH;         // 49*8 (wy f32 x4 | wx half2 x4)
    int*   s_off = (int*)(s_w + 49 * 8);           // 49*8 (ro x4 | co x4)

    const int n = blockIdx.x;
    const int tid = threadIdx.x;

    const int bidx = (int)rois[n * 5 + 0];

    if (tid < 49) {
        const float x1 = rois[n * 5 + 1] * SCALE_F - 0.5f;
        const float y1 = rois[n * 5 + 2] * SCALE_F - 0.5f;
        const float x2 = rois[n * 5 + 3] * SCALE_F - 0.5f;
        const float y2 = rois[n * 5 + 4] * SCALE_F - 0.5f;
        const float rw = fmaxf(x2 - x1, 1.0f);
        const float rh = fmaxf(y2 - y1, 1.0f);
        const float bw = rw * (1.0f / Pn);
        const float bh = rh * (1.0f / Pn);

        const int ph = tid / 7;
        const int pw = tid - ph * 7;
        const float ox = offset[n * 98 + tid];
        const float oy = offset[n * 98 + 49 + tid];
        const float ybase = y1 + (float)ph * bh + GAMMA_F * rh * oy;
        const float xbase = x1 + (float)pw * bw + GAMMA_F * rw * ox;

        // ---- y direction: 4 samples -> weights over 4 contiguous rows ----
        float wy[4] = {0.f, 0.f, 0.f, 0.f};
        int   y0a[4];
        float lya[4], va[4];
        int rmin = Hn;
#pragma unroll
        for (int i = 0; i < 4; i++) {
            const float s  = ((float)i + 0.5f) * 0.25f;
            const float ys = ybase + s * bh;
            const float v  = (ys > -1.0f && ys < (float)Hn) ? 0.25f : 0.0f;
            const float yc = fminf(fmaxf(ys, 0.0f), (float)(Hn - 1));
            const int   y0 = (int)yc;
            y0a[i] = y0; lya[i] = yc - (float)y0; va[i] = v;
            rmin = min(rmin, y0);
        }
#pragma unroll
        for (int i = 0; i < 4; i++) {
            const int sl0 = min(y0a[i] - rmin, 3);
            const int sl1 = min(min(y0a[i] + 1, Hn - 1) - rmin, 3);
            wy[sl0] += (1.0f - lya[i]) * va[i];
            wy[sl1] += lya[i] * va[i];
        }

        // ---- x direction ----
        float wx[4] = {0.f, 0.f, 0.f, 0.f};
        int   x0a[4];
        float lxa[4], vxa[4];
        int cmin = Wn;
#pragma unroll
        for (int j = 0; j < 4; j++) {
            const float s  = ((float)j + 0.5f) * 0.25f;
            const float xs = xbase + s * bw;
            const float v  = (xs > -1.0f && xs < (float)Wn) ? 0.25f : 0.0f;
            const float xc = fminf(fmaxf(xs, 0.0f), (float)(Wn - 1));
            const int   x0 = (int)xc;
            x0a[j] = x0; lxa[j] = xc - (float)x0; vxa[j] = v;
            cmin = min(cmin, x0);
        }
#pragma unroll
        for (int j = 0; j < 4; j++) {
            const int sl0 = min(x0a[j] - cmin, 3);
            const int sl1 = min(min(x0a[j] + 1, Wn - 1) - cmin, 3);
            wx[sl0] += (1.0f - lxa[j]) * vxa[j];
            wx[sl1] += lxa[j] * vxa[j];
        }

        // ---- record: wy (f32 x4) | wx (half2-broadcast x4) ; ro x4 | co x4 ----
#pragma unroll
        for (int k = 0; k < 4; k++) {
            s_w[tid * 8 + k] = wy[k];
            const unsigned short hb = __half_as_ushort(__float2half_rn(wx[k]));
            ((unsigned*)s_w)[tid * 8 + 4 + k] = (unsigned)hb * 0x10001u;
            s_off[tid * 8 + k]     = min(rmin + k, Hn - 1) * (Wn * Cn);
            s_off[tid * 8 + 4 + k] = min(cmin + k, Wn - 1) * Cn;
        }
    }
    __syncthreads();

    // ---- gather: thread = (bin slice bs 0..15) x (channel oct c8 0..31) ----
    const int c8 = tid & 31;
    const int bs = tid >> 5;
    const __half* base = g_xt + (size_t)(bidx * Hn * Wn) * Cn + c8 * 8;
    float* sout_row = s_out + c8 * 8;

    // 2-bin unrolled: pairs (bin, bin+16), stride 32
    int bin = bs;
    for (; bin + 16 < 49; bin += 32) {
        float4 aLo, aHi, bLo, bHi;
        gather_bin(base, s_w, s_off, bin,      aLo, aHi);
        gather_bin(base, s_w, s_off, bin + 16, bLo, bHi);
        *(float4*)(sout_row + bin        * SOUT_PITCH)     = aLo;
        *(float4*)(sout_row + bin        * SOUT_PITCH + 4) = aHi;
        *(float4*)(sout_row + (bin + 16) * SOUT_PITCH)     = bLo;
        *(float4*)(sout_row + (bin + 16) * SOUT_PITCH + 4) = bHi;
    }
    for (; bin < 49; bin += 16) {
        float4 aLo, aHi;
        gather_bin(base, s_w, s_off, bin, aLo, aHi);
        *(float4*)(sout_row + bin * SOUT_PITCH)     = aLo;
        *(float4*)(sout_row + bin * SOUT_PITCH + 4) = aHi;
    }
    __syncthreads();

    // ---- coalesced streaming store of the ROI's contiguous [C][49] chunk ----
    float* o = out + (size_t)n * (Cn * 49);
    for (int l = tid; l < Cn * 49; l += 512) {
        const int c = l / 49;
        const int b = l - c * 49;
        __stcs(o + l, s_out[b * SOUT_PITCH + c]);
    }
}

extern "C" void kernel_launch(void* const* d_in, const int* in_sizes, int n_in,
                              void* d_out, int out_size) {
    const float* x      = (const float*)d_in[0];
    const float* rois   = (const float*)d_in[1];
    const float* offset = (const float*)d_in[2];
    float* out = (float*)d_out;

    // NCHW fp32 -> NHWC fp16
    dim3 tgrid(Wn / 32, Cn / 128, Bn * Hn);
    transpose_nchw_nhwc<<<tgrid, 256>>>(x);

    const int smem_bytes = (49 * SOUT_PITCH + 49 * 8) * sizeof(float) + 49 * 8 * sizeof(int);
    static bool attr_set = false;
    if (!attr_set) {
        cudaFuncSetAttribute(dcn_pool_kernel,
                             cudaFuncAttributeMaxDynamicSharedMemorySize, smem_bytes);
        attr_set = true;
    }
    dcn_pool_kernel<<<N_ROIS, 512, smem_bytes>>>(rois, offset, out);
}